// round 6
// baseline (speedup 1.0000x reference)
#include <cuda_runtime.h>
#include <math_constants.h>

// queries/keys/values: 8192 fp32 each; 8 segments of 1024 contiguous floats.
// dists[i][j] = exact DTW(|a-b|) between q-seg i and k-seg j (1024x1024 DP).
// A = softmax(0.5*dists, axis=-1); out = A @ value-segments.

#define N_SEG    8
#define SEG_LEN  1024
#define C_COLS   8                            // columns per thread
#define R_ROWS   4                            // rows per pipeline step
#define P_THR    128
#define N_BLK    (SEG_LEN / R_ROWS)           // 256 row-blocks
#define SKEW_W   4                            // extra skew per warp seam
#define SIG_MAX  (P_THR - 1 + SKEW_W * 3)     // 139
#define N_STEPS  (N_BLK + SIG_MAX)            // 395
#define SUPER    4                            // steps per __syncthreads
#define NSUPER   ((N_STEPS + SUPER - 1) / SUPER)   // 99 -> 396 executed steps
#define RING     16

__device__ float        g_dists[N_SEG * N_SEG];
__device__ unsigned int g_count = 0;          // self-resetting via atomicInc wrap

// One CTA per (qi,kj). Pipelined 4x8 register-tile DTW, tile emitted in
// COLUMN-MAJOR order: each column's 4 cells form a short vertical chain
// (~8 cyc/link); consecutive columns overlap with ~8-cyc offset -> the step
// is issue-bound, not chain-bound. Thread t owns cols [8t,8t+8); skew
// sigma = t + 4*warp; step s -> row-block b = s - sigma. INF is a fixed
// point of the recurrence, so threads inside their executed window run
// branch-free on INF state and produce exactly the correct virtual
// boundaries. Intra-warp handoff: shfl_up. Warp seams: 16-slot smem ring;
// consumer prefetches slot s-4 at end of step s (>=1 barrier in between,
// SUPER==SKEW_W). Warps skip entire supersteps outside their activity
// window (with a 1-superstep warmup prefix so lane 0's ring prefetch is
// warm at the first real step).
__global__ __launch_bounds__(P_THR, 1)
void dtw_kernel(const float* __restrict__ q, const float* __restrict__ k,
                const float* __restrict__ values, float* __restrict__ out_g) {
    const int qi = blockIdx.x;
    const int kj = blockIdx.y;
    const float* __restrict__ xrow = q + qi * SEG_LEN;
    const float* __restrict__ ycol = k + kj * SEG_LEN;

    __shared__ float  sx[SEG_LEN];
    __shared__ float4 ring[3][RING];           // [seam][slot] (4 boundary vals)
    __shared__ float  sA[N_SEG][N_SEG];
    __shared__ unsigned s_last;

    const int t    = threadIdx.x;
    const int lane = t & 31;
    const int warp = t >> 5;
    const int sigma = t + SKEW_W * warp;
    const float INF = CUDART_INF_F;

    for (int i = t; i < SEG_LEN / 4; i += P_THR)
        reinterpret_cast<float4*>(sx)[i] = reinterpret_cast<const float4*>(xrow)[i];
    {
        const float4 inf4 = make_float4(INF, INF, INF, INF);
        float4* rp = &ring[0][0];
        for (int i = t; i < 3 * RING; i += P_THR) rp[i] = inf4;
    }

    float y[C_COLS];
    {
        const float4* y4 = reinterpret_cast<const float4*>(ycol + t * C_COLS);
        float4 a = y4[0], b = y4[1];
        y[0]=a.x; y[1]=a.y; y[2]=a.z; y[3]=a.w;
        y[4]=b.x; y[5]=b.y; y[6]=b.z; y[7]=b.w;
    }

    float U[C_COLS];                 // d[r0-1, base+j] (top boundary, rolling)
    float lv[R_ROWS];                // incoming left boundary for this block
#pragma unroll
    for (int j = 0; j < C_COLS; j++) U[j] = INF;
#pragma unroll
    for (int r = 0; r < R_ROWS; r++) lv[r] = INF;
    float carry = (t == 0) ? 0.0f : INF;   // d[r0-1, base-1] entering a block
    float res = 0.0f;

    __syncthreads();

    float xr[R_ROWS];
    {   // preload x rows for step (4*wstart) : clamps below via same formula
        const float4 a = reinterpret_cast<const float4*>(sx)[0];
        xr[0]=a.x; xr[1]=a.y; xr[2]=a.z; xr[3]=a.w;
    }

    // Executed superstep window for this warp:
    //   first real step of warp = 36*warp; warmup starts 4 steps earlier so
    //   lane0's ring prefetch (end of step 36w-1, slot 36w-5) lands before use.
    const int wstart = (warp == 0) ? 0 : (9 * warp - 1);
    const int wlast  = (36 * warp + 31 + SKEW_W * 0 + 255 + SKEW_W * warp) >> 2; // (36w+286)/4

    for (int sup = 0; sup < NSUPER; sup++) {
        if (sup >= wstart && sup <= wlast) {
            int s = sup * SUPER;
#pragma unroll
            for (int u = 0; u < SUPER; u++, s++) {
                const int b = s - sigma;

                // ---- 4x8 tile, column-major ----
                float pc0 = lv[0], pc1 = lv[1], pc2 = lv[2], pc3 = lv[3];
                float uleft = carry;             // old U[j-1]
#pragma unroll
                for (int j = 0; j < C_COLS; j++) {
                    const float Uj = U[j];
                    const float c0 = fabsf(xr[0] - y[j]) + fminf(fminf(Uj,  uleft), pc0);
                    const float c1 = fabsf(xr[1] - y[j]) + fminf(fminf(pc1, pc0), c0);
                    const float c2 = fabsf(xr[2] - y[j]) + fminf(fminf(pc2, pc1), c1);
                    const float c3 = fabsf(xr[3] - y[j]) + fminf(fminf(pc3, pc2), c2);
                    U[j]  = c3;                  // new top boundary for next block
                    uleft = Uj;
                    pc0 = c0; pc1 = c1; pc2 = c2; pc3 = c3;
                }
                // pc0..pc3 = right boundary ov[0..3] of this block

                res   = (b == N_BLK - 1) ? pc3 : res;   // d[1023, base+7]
                carry = lv[3];

                // intra-warp handoff for next step
                lv[0] = __shfl_up_sync(0xffffffffu, pc0, 1);
                lv[1] = __shfl_up_sync(0xffffffffu, pc1, 1);
                lv[2] = __shfl_up_sync(0xffffffffu, pc2, 1);
                lv[3] = __shfl_up_sync(0xffffffffu, pc3, 1);

                if (lane == 31 && warp < 3)      // seam producer
                    ring[warp][s & (RING - 1)] = make_float4(pc0, pc1, pc2, pc3);

                if (lane == 0) {                 // seam consumer (for step s+1)
                    if (warp != 0) {
                        const float4 a = ring[warp - 1][(s - SKEW_W) & (RING - 1)];
                        lv[0]=a.x; lv[1]=a.y; lv[2]=a.z; lv[3]=a.w;
                    } else {
                        lv[0]=INF; lv[1]=INF; lv[2]=INF; lv[3]=INF;
                    }
                }

                // prefetch x rows for next step (clamped; garbage is harmless)
                const int bn = s + 1 - sigma;
                const int i4 = min(max(bn, 0), N_BLK - 1);
                const float4 xa = reinterpret_cast<const float4*>(sx)[i4];
                xr[0]=xa.x; xr[1]=xa.y; xr[2]=xa.z; xr[3]=xa.w;
            }
        }
        __syncthreads();
    }

    if (t == P_THR - 1) g_dists[qi * N_SEG + kj] = res;

    // ---- fused epilogue: last CTA to arrive does softmax + A @ V ----
    __threadfence();
    if (t == 0) s_last = atomicInc(&g_count, N_SEG * N_SEG - 1);
    __syncthreads();
    if (s_last != N_SEG * N_SEG - 1) return;
    __threadfence();

    if (t < N_SEG) {
        float l[N_SEG];
        float m = -INF;
#pragma unroll
        for (int j = 0; j < N_SEG; j++) {
            l[j] = 0.5f * g_dists[t * N_SEG + j];   // scale = 1/sqrt(4)
            m = fmaxf(m, l[j]);
        }
        float ssum = 0.0f;
#pragma unroll
        for (int j = 0; j < N_SEG; j++) {
            l[j] = expf(l[j] - m);
            ssum += l[j];
        }
        const float inv = 1.0f / ssum;
#pragma unroll
        for (int j = 0; j < N_SEG; j++) sA[t][j] = l[j] * inv;
    }
    __syncthreads();

    const float4* v4 = reinterpret_cast<const float4*>(values);
    float4* o4 = reinterpret_cast<float4*>(out_g);
#pragma unroll
    for (int n = 0; n < 16; n++) {
        const int g = t + n * P_THR;                // float4 index (2048 total)
        const int i = g >> 8;                       // segment (256 float4/seg)
        const int c = g & 255;
        float4 acc = make_float4(0.f, 0.f, 0.f, 0.f);
#pragma unroll
        for (int j = 0; j < N_SEG; j++) {
            const float w = sA[i][j];
            const float4 v = v4[j * 256 + c];
            acc.x += w * v.x;
            acc.y += w * v.y;
            acc.z += w * v.z;
            acc.w += w * v.w;
        }
        o4[g] = acc;
    }
}

extern "C" void kernel_launch(void* const* d_in, const int* in_sizes, int n_in,
                              void* d_out, int out_size) {
    const float* queries = (const float*)d_in[0];
    const float* keys    = (const float*)d_in[1];
    const float* values  = (const float*)d_in[2];
    float* out = (float*)d_out;

    dim3 grid(N_SEG, N_SEG);
    dtw_kernel<<<grid, P_THR>>>(queries, keys, values, out);
}

// round 7
// speedup vs baseline: 1.5609x; 1.5609x over previous
#include <cuda_runtime.h>
#include <math_constants.h>

// queries/keys/values: 8192 fp32 each; 8 segments of 1024 contiguous floats.
// dists[i][j] = exact DTW(|a-b|) between q-seg i and k-seg j (1024x1024 DP).
// A = softmax(0.5*dists, axis=-1); out = A @ value-segments.

#define N_SEG    8
#define SEG_LEN  1024
#define C_COLS   8                            // columns per thread
#define R_ROWS   4                            // rows per pipeline step
#define P_THR    128
#define N_BLK    (SEG_LEN / R_ROWS)           // 256 row-blocks
#define SKEW_W   4                            // extra skew per warp seam
#define SIG_MAX  (P_THR - 1 + SKEW_W * 3)     // 139
#define N_STEPS  (N_BLK + SIG_MAX)            // 395
#define SUPER    4                            // steps per __syncthreads
#define NSUPER   ((N_STEPS + SUPER - 1) / SUPER)   // 99 -> 396 executed steps
#define RING     16

__device__ float        g_dists[N_SEG * N_SEG];
__device__ unsigned int g_count = 0;          // self-resetting via atomicInc wrap

// One CTA per (qi,kj). Fully branch-free pipelined 4x8 register-tile DTW.
// Thread t owns cols [8t,8t+8); skew sigma = t + 4*warp; step s -> block
// b = s - sigma. INF is a fixed point of the recurrence, so out-of-window
// threads run the same code on INF state and produce exactly the correct
// virtual boundaries (x reads clamped; garbage x only meets INF state or
// post-drain threads).
// Per-step overhead minimized:
//   - seam consumer: ALL lanes broadcast-load ring[(warp-1)&3][s-4] (row 3 is
//     a permanent all-INF row for warp 0), then SEL per element for lane 0.
//   - seam producer: one predicated STS.128 @(lane==31 && warp<3).
//   - x rows: 4 clamped LDS.128 hoisted to once per superstep.
//   - barrier once per SUPER=4 steps; ring slot s-4 is always written in a
//     previous superstep, so one barrier separates producer and consumer.
__global__ __launch_bounds__(P_THR, 1)
void dtw_kernel(const float* __restrict__ q, const float* __restrict__ k,
                const float* __restrict__ values, float* __restrict__ out_g) {
    const int qi = blockIdx.x;
    const int kj = blockIdx.y;
    const float* __restrict__ xrow = q + qi * SEG_LEN;
    const float* __restrict__ ycol = k + kj * SEG_LEN;

    __shared__ float  sx[SEG_LEN];
    __shared__ float4 ring[4][RING];          // row 3: permanent INF row
    __shared__ float  sA[N_SEG][N_SEG];
    __shared__ unsigned s_last;

    const int t    = threadIdx.x;
    const int lane = t & 31;
    const int warp = t >> 5;
    const int sigma = t + SKEW_W * warp;
    const int rdrow = (warp + 3) & 3;         // warp-1; warp0 -> 3 (INF row)
    const float INF = CUDART_INF_F;

    for (int i = t; i < SEG_LEN / 4; i += P_THR)
        reinterpret_cast<float4*>(sx)[i] = reinterpret_cast<const float4*>(xrow)[i];
    {
        const float4 inf4 = make_float4(INF, INF, INF, INF);
        float4* rp = &ring[0][0];
        for (int i = t; i < 4 * RING; i += P_THR) rp[i] = inf4;
    }

    float y[C_COLS];
    {
        const float4* y4 = reinterpret_cast<const float4*>(ycol + t * C_COLS);
        float4 a = y4[0], b = y4[1];
        y[0]=a.x; y[1]=a.y; y[2]=a.z; y[3]=a.w;
        y[4]=b.x; y[5]=b.y; y[6]=b.z; y[7]=b.w;
    }

    float U[C_COLS];                  // d[r0-1, base+j] (top boundary, rolling)
#pragma unroll
    for (int j = 0; j < C_COLS; j++) U[j] = INF;
    float lv0 = INF, lv1 = INF, lv2 = INF, lv3 = INF;   // left boundary
    float carry = (t == 0) ? 0.0f : INF;  // d[r0-1, base-1] entering a block
    float res = 0.0f;

    __syncthreads();

    const float4* sx4 = reinterpret_cast<const float4*>(sx);

    for (int sup = 0; sup < NSUPER; sup++) {
        const int b0 = sup * SUPER - sigma;
        // x rows for the 4 steps of this superstep (clamped; garbage rows
        // only ever meet INF state or post-drain threads -> harmless).
        const int i0 = min(max(b0,     0), N_BLK - 1);
        const int i1 = min(max(b0 + 1, 0), N_BLK - 1);
        const int i2 = min(max(b0 + 2, 0), N_BLK - 1);
        const int i3 = min(max(b0 + 3, 0), N_BLK - 1);
        float4 X[SUPER];
        X[0] = sx4[i0]; X[1] = sx4[i1]; X[2] = sx4[i2]; X[3] = sx4[i3];

#pragma unroll
        for (int u = 0; u < SUPER; u++) {
            const int s = sup * SUPER + u;
            const int b = b0 + u;
            const float4 xv = X[u];

            // ---- 4x8 tile, column-major ----
            float pc0 = lv0, pc1 = lv1, pc2 = lv2, pc3 = lv3;
            float uleft = carry;              // old U[j-1]
#pragma unroll
            for (int j = 0; j < C_COLS; j++) {
                const float Uj = U[j];
                const float c0 = fabsf(xv.x - y[j]) + fminf(fminf(Uj,  uleft), pc0);
                const float c1 = fabsf(xv.y - y[j]) + fminf(fminf(pc1, pc0), c0);
                const float c2 = fabsf(xv.z - y[j]) + fminf(fminf(pc2, pc1), c1);
                const float c3 = fabsf(xv.w - y[j]) + fminf(fminf(pc3, pc2), c2);
                U[j]  = c3;                   // new top boundary for next block
                uleft = Uj;
                pc0 = c0; pc1 = c1; pc2 = c2; pc3 = c3;
            }
            // pc0..pc3 = right boundary of this block

            res   = (b == N_BLK - 1) ? pc3 : res;    // d[1023, base+7]
            carry = lv3;

            // intra-warp handoff for next step
            const float n0 = __shfl_up_sync(0xffffffffu, pc0, 1);
            const float n1 = __shfl_up_sync(0xffffffffu, pc1, 1);
            const float n2 = __shfl_up_sync(0xffffffffu, pc2, 1);
            const float n3 = __shfl_up_sync(0xffffffffu, pc3, 1);

            // seam producer: single predicated wide store
            if (lane == 31 && warp < 3)
                ring[warp][s & (RING - 1)] = make_float4(pc0, pc1, pc2, pc3);

            // seam consumer: broadcast load + per-element select (no branch)
            const float4 rv = ring[rdrow][(s - SKEW_W) & (RING - 1)];
            const bool l0 = (lane == 0);
            lv0 = l0 ? rv.x : n0;
            lv1 = l0 ? rv.y : n1;
            lv2 = l0 ? rv.z : n2;
            lv3 = l0 ? rv.w : n3;
        }
        __syncthreads();
    }

    if (t == P_THR - 1) g_dists[qi * N_SEG + kj] = res;

    // ---- fused epilogue: last CTA to arrive does softmax + A @ V ----
    __threadfence();
    if (t == 0) s_last = atomicInc(&g_count, N_SEG * N_SEG - 1);
    __syncthreads();
    if (s_last != N_SEG * N_SEG - 1) return;
    __threadfence();

    if (t < N_SEG) {
        float l[N_SEG];
        float m = -INF;
#pragma unroll
        for (int j = 0; j < N_SEG; j++) {
            l[j] = 0.5f * g_dists[t * N_SEG + j];    // scale = 1/sqrt(4)
            m = fmaxf(m, l[j]);
        }
        float ssum = 0.0f;
#pragma unroll
        for (int j = 0; j < N_SEG; j++) {
            l[j] = expf(l[j] - m);
            ssum += l[j];
        }
        const float inv = 1.0f / ssum;
#pragma unroll
        for (int j = 0; j < N_SEG; j++) sA[t][j] = l[j] * inv;
    }
    __syncthreads();

    const float4* v4 = reinterpret_cast<const float4*>(values);
    float4* o4 = reinterpret_cast<float4*>(out_g);
#pragma unroll
    for (int n = 0; n < 16; n++) {
        const int g = t + n * P_THR;                 // float4 index (2048 total)
        const int i = g >> 8;                        // segment (256 float4/seg)
        const int c = g & 255;
        float4 acc = make_float4(0.f, 0.f, 0.f, 0.f);
#pragma unroll
        for (int j = 0; j < N_SEG; j++) {
            const float w = sA[i][j];
            const float4 v = v4[j * 256 + c];
            acc.x += w * v.x;
            acc.y += w * v.y;
            acc.z += w * v.z;
            acc.w += w * v.w;
        }
        o4[g] = acc;
    }
}

extern "C" void kernel_launch(void* const* d_in, const int* in_sizes, int n_in,
                              void* d_out, int out_size) {
    const float* queries = (const float*)d_in[0];
    const float* keys    = (const float*)d_in[1];
    const float* values  = (const float*)d_in[2];
    float* out = (float*)d_out;

    dim3 grid(N_SEG, N_SEG);
    dtw_kernel<<<grid, P_THR>>>(queries, keys, values, out);
}

// round 8
// speedup vs baseline: 1.8514x; 1.1861x over previous
#include <cuda_runtime.h>
#include <math_constants.h>

// queries/keys/values: 8192 fp32 each; 8 segments of 1024 contiguous floats.
// dists[i][j] = exact DTW(|a-b|) between q-seg i and k-seg j (1024x1024 DP).
// A = softmax(0.5*dists, axis=-1); out = A @ value-segments.

#define N_SEG    8
#define SEG_LEN  1024
#define C_COLS   8                            // columns per thread
#define R_ROWS   4                            // rows per pipeline step
#define P_THR    128
#define N_BLK    (SEG_LEN / R_ROWS)           // 256 row-blocks
#define SKEW_W   8                            // extra skew per warp seam
#define SIG_MAX  (P_THR - 1 + SKEW_W * 3)     // 151
#define N_STEPS  (N_BLK + SIG_MAX)            // 407
#define SUPER    8                            // steps per __syncthreads
#define NSUPER   ((N_STEPS + SUPER - 1) / SUPER)   // 51 -> 408 executed steps
#define RING     16

__device__ float        g_dists[N_SEG * N_SEG];
__device__ unsigned int g_count = 0;          // self-resetting via atomicInc wrap

// One CTA per (qi,kj). Fully branch-free pipelined 4x8 register-tile DTW.
// Thread t owns cols [8t,8t+8); skew sigma = t + 8*warp; step s -> block
// b = s - sigma. INF is a fixed point of the recurrence, so out-of-window
// threads run the same code on INF state and produce exactly the correct
// virtual boundaries (x reads clamped; garbage x only meets INF state or
// post-drain threads).
// Per-step overhead minimized:
//   - barrier only every SUPER=8 steps (SKEW_W=8 seam slack); ring slot s-8
//     is always written in the previous superstep -> exactly one barrier
//     between seam write and read; slot overwrite is >=1 barrier after the
//     last read (RING=16).
//   - seam consumer: ALL lanes broadcast-load ring[(warp-1)&3][s-8] BEFORE
//     the tile (LDS latency buried), then SEL per element for lane 0
//     (row 3 of the ring is a permanent all-INF row for warp 0).
//   - seam producer: one predicated STS.128 @(lane==31 && warp<3).
//   - x rows: 8 clamped LDS.128 hoisted to once per superstep.
__global__ __launch_bounds__(P_THR, 1)
void dtw_kernel(const float* __restrict__ q, const float* __restrict__ k,
                const float* __restrict__ values, float* __restrict__ out_g) {
    const int qi = blockIdx.x;
    const int kj = blockIdx.y;
    const float* __restrict__ xrow = q + qi * SEG_LEN;
    const float* __restrict__ ycol = k + kj * SEG_LEN;

    __shared__ float  sx[SEG_LEN];
    __shared__ float4 ring[4][RING];          // row 3: permanent INF row
    __shared__ float  sA[N_SEG][N_SEG];
    __shared__ unsigned s_last;

    const int t    = threadIdx.x;
    const int lane = t & 31;
    const int warp = t >> 5;
    const int sigma = t + SKEW_W * warp;
    const int rdrow = (warp + 3) & 3;         // warp-1; warp0 -> 3 (INF row)
    const float INF = CUDART_INF_F;

    for (int i = t; i < SEG_LEN / 4; i += P_THR)
        reinterpret_cast<float4*>(sx)[i] = reinterpret_cast<const float4*>(xrow)[i];
    {
        const float4 inf4 = make_float4(INF, INF, INF, INF);
        float4* rp = &ring[0][0];
        for (int i = t; i < 4 * RING; i += P_THR) rp[i] = inf4;
    }

    float y[C_COLS];
    {
        const float4* y4 = reinterpret_cast<const float4*>(ycol + t * C_COLS);
        float4 a = y4[0], b = y4[1];
        y[0]=a.x; y[1]=a.y; y[2]=a.z; y[3]=a.w;
        y[4]=b.x; y[5]=b.y; y[6]=b.z; y[7]=b.w;
    }

    float U[C_COLS];                  // d[r0-1, base+j] (top boundary, rolling)
#pragma unroll
    for (int j = 0; j < C_COLS; j++) U[j] = INF;
    float lv0 = INF, lv1 = INF, lv2 = INF, lv3 = INF;   // left boundary
    float carry = (t == 0) ? 0.0f : INF;  // d[r0-1, base-1] entering a block
    float res = 0.0f;

    __syncthreads();

    const float4* sx4 = reinterpret_cast<const float4*>(sx);

    for (int sup = 0; sup < NSUPER; sup++) {
        const int b0 = sup * SUPER - sigma;
        // x rows for the 8 steps of this superstep (clamped; garbage rows
        // only ever meet INF state or post-drain threads -> harmless).
        float4 X[SUPER];
#pragma unroll
        for (int u = 0; u < SUPER; u++) {
            const int iu = min(max(b0 + u, 0), N_BLK - 1);
            X[u] = sx4[iu];
        }

#pragma unroll
        for (int u = 0; u < SUPER; u++) {
            const int s = sup * SUPER + u;
            const int b = b0 + u;
            const float4 xv = X[u];

            // seam consumer pre-load (independent of the tile; latency buried)
            const float4 rv = ring[rdrow][(s - SKEW_W) & (RING - 1)];

            // ---- 4x8 tile, column-major ----
            float pc0 = lv0, pc1 = lv1, pc2 = lv2, pc3 = lv3;
            float uleft = carry;              // old U[j-1]
#pragma unroll
            for (int j = 0; j < C_COLS; j++) {
                const float Uj = U[j];
                const float c0 = fabsf(xv.x - y[j]) + fminf(fminf(Uj,  uleft), pc0);
                const float c1 = fabsf(xv.y - y[j]) + fminf(fminf(pc1, pc0), c0);
                const float c2 = fabsf(xv.z - y[j]) + fminf(fminf(pc2, pc1), c1);
                const float c3 = fabsf(xv.w - y[j]) + fminf(fminf(pc3, pc2), c2);
                U[j]  = c3;                   // new top boundary for next block
                uleft = Uj;
                pc0 = c0; pc1 = c1; pc2 = c2; pc3 = c3;
            }
            // pc0..pc3 = right boundary of this block

            res   = (b == N_BLK - 1) ? pc3 : res;    // d[1023, base+7]
            carry = lv3;

            // intra-warp handoff for next step
            const float n0 = __shfl_up_sync(0xffffffffu, pc0, 1);
            const float n1 = __shfl_up_sync(0xffffffffu, pc1, 1);
            const float n2 = __shfl_up_sync(0xffffffffu, pc2, 1);
            const float n3 = __shfl_up_sync(0xffffffffu, pc3, 1);

            // seam producer: single predicated wide store
            if (lane == 31 && warp < 3)
                ring[warp][s & (RING - 1)] = make_float4(pc0, pc1, pc2, pc3);

            // seam consumer select (no branch)
            const bool l0 = (lane == 0);
            lv0 = l0 ? rv.x : n0;
            lv1 = l0 ? rv.y : n1;
            lv2 = l0 ? rv.z : n2;
            lv3 = l0 ? rv.w : n3;
        }
        __syncthreads();
    }

    if (t == P_THR - 1) g_dists[qi * N_SEG + kj] = res;

    // ---- fused epilogue: last CTA to arrive does softmax + A @ V ----
    __threadfence();
    if (t == 0) s_last = atomicInc(&g_count, N_SEG * N_SEG - 1);
    __syncthreads();
    if (s_last != N_SEG * N_SEG - 1) return;
    __threadfence();

    if (t < N_SEG) {
        float l[N_SEG];
        float m = -INF;
#pragma unroll
        for (int j = 0; j < N_SEG; j++) {
            l[j] = 0.5f * g_dists[t * N_SEG + j];    // scale = 1/sqrt(4)
            m = fmaxf(m, l[j]);
        }
        float ssum = 0.0f;
#pragma unroll
        for (int j = 0; j < N_SEG; j++) {
            l[j] = expf(l[j] - m);
            ssum += l[j];
        }
        const float inv = 1.0f / ssum;
#pragma unroll
        for (int j = 0; j < N_SEG; j++) sA[t][j] = l[j] * inv;
    }
    __syncthreads();

    const float4* v4 = reinterpret_cast<const float4*>(values);
    float4* o4 = reinterpret_cast<float4*>(out_g);
#pragma unroll
    for (int n = 0; n < 16; n++) {
        const int g = t + n * P_THR;                 // float4 index (2048 total)
        const int i = g >> 8;                        // segment (256 float4/seg)
        const int c = g & 255;
        float4 acc = make_float4(0.f, 0.f, 0.f, 0.f);
#pragma unroll
        for (int j = 0; j < N_SEG; j++) {
            const float w = sA[i][j];
            const float4 v = v4[j * 256 + c];
            acc.x += w * v.x;
            acc.y += w * v.y;
            acc.z += w * v.z;
            acc.w += w * v.w;
        }
        o4[g] = acc;
    }
}

extern "C" void kernel_launch(void* const* d_in, const int* in_sizes, int n_in,
                              void* d_out, int out_size) {
    const float* queries = (const float*)d_in[0];
    const float* keys    = (const float*)d_in[1];
    const float* values  = (const float*)d_in[2];
    float* out = (float*)d_out;

    dim3 grid(N_SEG, N_SEG);
    dtw_kernel<<<grid, P_THR>>>(queries, keys, values, out);
}